// round 15
// baseline (speedup 1.0000x reference)
#include <cuda_runtime.h>
#include <cuda_fp16.h>
#include <cstdint>
#include <math.h>

// Problem constants
#define BB 8
#define NN_ 2048
#define DD 256
#define HH 256
#define ROWS (BB*NN_)          // 16384
#define ALPHA 0.2f

// ---------------- scratch (device globals) ---------------------------------
__device__ __half   g_WhT [(size_t)ROWS*HH];     // fp16 Wh^T [b][h][i]
__device__ __half   g_ws  [(size_t)ROWS*NN_];    // fp16 attention weights [r][j]
__device__ __half   g_go16[(size_t)ROWS*HH];     // fp16 graph_out
__device__ __half   g_gh16[(size_t)ROWS*3*HH];   // fp16 gh
__device__ __half   g_x16 [(size_t)ROWS*HH];     // fp16 x
__device__ __half   g_wih16[3*HH*HH];
__device__ __half   g_whh16[3*HH*HH];
__device__ __half   g_wt16[HH*DD];               // fp16 W^T [h][d]
__device__ float    g_av [2*DD];                 // W@a1 | W@a2
__device__ float    g_Wh1[ROWS];
__device__ float    g_Wh2[ROWS];
__device__ float    g_rs [ROWS];

// ---------------- helpers ---------------------------------------------------
__device__ __forceinline__ void mma_f16(float* d, const uint32_t* a, const uint32_t* b) {
    asm volatile("mma.sync.aligned.m16n8k16.row.col.f32.f16.f16.f32 "
        "{%0,%1,%2,%3}, {%4,%5,%6,%7}, {%8,%9}, {%0,%1,%2,%3};\n"
        : "+f"(d[0]), "+f"(d[1]), "+f"(d[2]), "+f"(d[3])
        : "r"(a[0]), "r"(a[1]), "r"(a[2]), "r"(a[3]), "r"(b[0]), "r"(b[1]));
}
__device__ __forceinline__ void cp16(void* smem, const void* gmem) {
    uint32_t s = (uint32_t)__cvta_generic_to_shared(smem);
    asm volatile("cp.async.cg.shared.global [%0], [%1], 16;\n" :: "r"(s), "l"(gmem));
}
__device__ __forceinline__ void cp_commit() { asm volatile("cp.async.commit_group;\n" ::: "memory"); }
__device__ __forceinline__ void cp_wait0()  { asm volatile("cp.async.wait_group 0;\n" ::: "memory"); }
__device__ __forceinline__ void cp_wait1()  { asm volatile("cp.async.wait_group 1;\n" ::: "memory"); }

#define AST 36     // [row][k-word] stride: frag LDS bank = (4g+t)%32, conflict-free

// ---------------- fused fp32 -> fp16 converter (x, w_ih, w_hh in one) ------
__global__ __launch_bounds__(256)
void cvt_all(const float* __restrict__ x,  __half* __restrict__ x16,
             const float* __restrict__ wi, __half* __restrict__ wi16,
             const float* __restrict__ wh, __half* __restrict__ wh16)
{
    int bid = blockIdx.x;
    const float* src; __half* dst; int base;
    if (bid < 2048)      { src = x;  dst = x16;  base = bid * 2048; }
    else if (bid < 2144) { src = wi; dst = wi16; base = (bid - 2048) * 2048; }
    else                 { src = wh; dst = wh16; base = (bid - 2144) * 2048; }
    int i = base + threadIdx.x * 8;
    float4 v0 = *(const float4*)(src + i);
    float4 v1 = *(const float4*)(src + i + 4);
    __half2 h[4] = { __floats2half2_rn(v0.x, v0.y), __floats2half2_rn(v0.z, v0.w),
                     __floats2half2_rn(v1.x, v1.y), __floats2half2_rn(v1.z, v1.w) };
    *(uint4*)(dst + i) = *(uint4*)h;
}

// ---------------- W[d][h] -> WT16[h][d] fp16 transpose ---------------------
__global__ void cvt_wT(const float* __restrict__ W, __half* __restrict__ WT)
{
    __shared__ float tle[32][33];
    const int h0 = blockIdx.x * 32, d0 = blockIdx.y * 32;
    const int tx = threadIdx.x, ty = threadIdx.y;    // 32 x 8
#pragma unroll
    for (int k = 0; k < 4; k++)
        tle[ty + 8 * k][tx] = W[(size_t)(d0 + ty + 8 * k) * HH + h0 + tx];
    __syncthreads();
#pragma unroll
    for (int k = 0; k < 4; k++)
        WT[(size_t)(h0 + ty + 8 * k) * DD + d0 + tx] = __float2half(tle[tx][ty + 8 * k]);
}

// ---------------- av = [W@a1 | W@a2]  (tiny fp32 GEMV) ---------------------
__global__ __launch_bounds__(256)
void av_gemv(const float* __restrict__ W, const float* __restrict__ a,
             float* __restrict__ av)
{
    const int warp = threadIdx.x >> 5, lane = threadIdx.x & 31;
    const int d = blockIdx.x * 8 + warp;           // 0..255
    const float* wr = W + (size_t)d * HH + lane * 8;
    float4 w0 = *(const float4*)wr;
    float4 w1 = *(const float4*)(wr + 4);
    const float* a1 = a + lane * 8;
    const float* a2 = a + HH + lane * 8;
    float4 p0 = *(const float4*)a1, p1 = *(const float4*)(a1 + 4);
    float4 q0 = *(const float4*)a2, q1 = *(const float4*)(a2 + 4);
    float s1 = w0.x*p0.x + w0.y*p0.y + w0.z*p0.z + w0.w*p0.w
             + w1.x*p1.x + w1.y*p1.y + w1.z*p1.z + w1.w*p1.w;
    float s2 = w0.x*q0.x + w0.y*q0.y + w0.z*q0.z + w0.w*q0.w
             + w1.x*q1.x + w1.y*q1.y + w1.z*q1.z + w1.w*q1.w;
#pragma unroll
    for (int o = 16; o; o >>= 1) {
        s1 += __shfl_xor_sync(0xffffffffu, s1, o);
        s2 += __shfl_xor_sync(0xffffffffu, s2, o);
    }
    if (lane == 0) { av[d] = s1; av[DD + d] = s2; }
}

// ---------------- Wh1/Wh2 via associativity: Wh1 = x16 . av1 ---------------
__global__ __launch_bounds__(256)
void wh12_x(const __half* __restrict__ x16, const float* __restrict__ av,
            float* __restrict__ Wh1, float* __restrict__ Wh2)
{
    const int warp = threadIdx.x >> 5, lane = threadIdx.x & 31;
    const int r = blockIdx.x * 8 + warp;
    const __half* xr = x16 + (size_t)r * DD + lane * 8;
    uint4 xv = *(const uint4*)xr;                  // 8 halves
    const __half2* xh = (const __half2*)&xv;
    const float* a1 = av + lane * 8;
    const float* a2 = av + DD + lane * 8;
    float4 p0 = *(const float4*)a1, p1 = *(const float4*)(a1 + 4);
    float4 q0 = *(const float4*)a2, q1 = *(const float4*)(a2 + 4);
    float2 x0 = __half22float2(xh[0]);
    float2 x1 = __half22float2(xh[1]);
    float2 x2 = __half22float2(xh[2]);
    float2 x3 = __half22float2(xh[3]);
    float s1 = x0.x*p0.x + x0.y*p0.y + x1.x*p0.z + x1.y*p0.w
             + x2.x*p1.x + x2.y*p1.y + x3.x*p1.z + x3.y*p1.w;
    float s2 = x0.x*q0.x + x0.y*q0.y + x1.x*q0.z + x1.y*q0.w
             + x2.x*q1.x + x2.y*q1.y + x3.x*q1.z + x3.y*q1.w;
#pragma unroll
    for (int o = 16; o; o >>= 1) {
        s1 += __shfl_xor_sync(0xffffffffu, s1, o);
        s2 += __shfl_xor_sync(0xffffffffu, s2, o);
    }
    if (lane == 0) { Wh1[r] = s1; Wh2[r] = s2; }
}

// ---------------- whT GEMM: WhT[b][h][i] = WT16 @ x16^T (fp16 MMA) ---------
#define WT_SMEM_BYTES (4 * 128 * AST * 4)
__global__ __launch_bounds__(256, 2)
void whT_f16(const __half* __restrict__ WT16, const __half* __restrict__ x16,
             __half* __restrict__ WhT)
{
    extern __shared__ uint32_t dsm[];
    uint32_t* As[2] = { dsm, dsm + 128 * AST };
    uint32_t* Bs[2] = { dsm + 2 * 128 * AST, dsm + 3 * 128 * AST };

    const int tid  = threadIdx.x;
    const int warp = tid >> 5, lane = tid & 31;
    const int g = lane >> 2, t = lane & 3;
    const int wm = warp & 1, wn = warp >> 1;   // 2 m x 4 n
    const int m0 = blockIdx.y * 128;           // h block
    const int n0 = blockIdx.x * 128;           // global row block
    const int b  = n0 >> 11;
    const int ib = n0 & (NN_ - 1);

    auto issue = [&](int T, int st) {
#pragma unroll
        for (int s = 0; s < 4; s++) {
            int f = tid + 256 * s;
            int m = f >> 3, grp = f & 7;
            cp16(&As[st][m * AST + grp * 4], WT16 + (size_t)(m0 + m) * DD + T * 64 + grp * 8);
        }
#pragma unroll
        for (int s = 0; s < 4; s++) {
            int f = tid + 256 * s;
            int n = f >> 3, grp = f & 7;
            cp16(&Bs[st][n * AST + grp * 4], x16 + (size_t)(n0 + n) * DD + T * 64 + grp * 8);
        }
    };

    float acc[4][4][4] = {};

    issue(0, 0); cp_commit();

    for (int T = 0; T < 4; T++) {
        const int st = T & 1;
        if (T + 1 < 4) { issue(T + 1, st ^ 1); cp_commit(); cp_wait1(); }
        else           { cp_wait0(); }
        __syncthreads();

#pragma unroll
        for (int ks = 0; ks < 4; ks++) {
            const int kk = ks * 8;
            uint32_t af[4][4], bf[4][2];
#pragma unroll
            for (int mf = 0; mf < 4; mf++) {
                int r0 = wm * 64 + mf * 16 + g;
                af[mf][0] = As[st][(r0    ) * AST + kk + t];
                af[mf][1] = As[st][(r0 + 8) * AST + kk + t];
                af[mf][2] = As[st][(r0    ) * AST + kk + t + 4];
                af[mf][3] = As[st][(r0 + 8) * AST + kk + t + 4];
            }
#pragma unroll
            for (int nf = 0; nf < 4; nf++) {
                int c0 = wn * 32 + nf * 8 + g;
                bf[nf][0] = Bs[st][c0 * AST + kk + t];
                bf[nf][1] = Bs[st][c0 * AST + kk + t + 4];
            }
#pragma unroll
            for (int mf = 0; mf < 4; mf++)
#pragma unroll
                for (int nf = 0; nf < 4; nf++)
                    mma_f16(acc[mf][nf], af[mf], bf[nf]);
        }
        __syncthreads();
    }

#pragma unroll
    for (int mf = 0; mf < 4; mf++) {
        int h = m0 + wm * 64 + mf * 16 + g;
#pragma unroll
        for (int nf = 0; nf < 4; nf++) {
            int i = ib + wn * 32 + nf * 8 + 2 * t;
            *(__half2*)(WhT + (size_t)(b * HH + h)     * NN_ + i) =
                __floats2half2_rn(acc[mf][nf][0], acc[mf][nf][1]);
            *(__half2*)(WhT + (size_t)(b * HH + h + 8) * NN_ + i) =
                __floats2half2_rn(acc[mf][nf][2], acc[mf][nf][3]);
        }
    }
}

// ---------------- fused: adj -> masked softmax stats + fp16 ws matrix ------
__global__ __launch_bounds__(256)
void pack_stats(const int* __restrict__ adj, const float* __restrict__ Wh1,
                const float* __restrict__ Wh2, __half* __restrict__ ws,
                float* __restrict__ rsum)
{
    const int r = blockIdx.x;
    const int b = r >> 11;
    const int tid = threadIdx.x;
    const float w1 = Wh1[r];
    const float* Wh2b = Wh2 + (b << 11);

    const int4* ap = (const int4*)(adj + (size_t)r * NN_ + tid * 8);
    int4 a0 = ap[0], a1 = ap[1];
    float4 w0 = *(const float4*)(Wh2b + tid * 8);
    float4 w1v = *(const float4*)(Wh2b + tid * 8 + 4);

    int m[8] = { a0.x > 0, a0.y > 0, a0.z > 0, a0.w > 0,
                 a1.x > 0, a1.y > 0, a1.z > 0, a1.w > 0 };
    float wv[8] = { w0.x, w0.y, w0.z, w0.w, w1v.x, w1v.y, w1v.z, w1v.w };

    float lrv[8];
    float mx = -INFINITY;
#pragma unroll
    for (int k = 0; k < 8; k++) {
        float sv = w1 + wv[k];
        float lr = sv > 0.f ? sv : ALPHA * sv;
        lrv[k] = m[k] ? lr : -INFINITY;
        mx = fmaxf(mx, lrv[k]);
    }

    __shared__ float sred[8];
#pragma unroll
    for (int o = 16; o; o >>= 1) mx = fmaxf(mx, __shfl_xor_sync(0xffffffffu, mx, o));
    if ((tid & 31) == 0) sred[tid >> 5] = mx;
    __syncthreads();
    if (tid == 0) {
        float v = sred[0];
#pragma unroll
        for (int w = 1; w < 8; w++) v = fmaxf(v, sred[w]);
        sred[0] = v;
    }
    __syncthreads();
    mx = sred[0];

    float ev[8];
    float sum = 0.f;
#pragma unroll
    for (int k = 0; k < 8; k++) { ev[k] = __expf(lrv[k] - mx); sum += ev[k]; }
    __half2 hq[4];
#pragma unroll
    for (int k = 0; k < 4; k++) hq[k] = __floats2half2_rn(ev[2*k], ev[2*k+1]);
    *(uint4*)(ws + (size_t)r * NN_ + tid * 8) = *(uint4*)hq;

#pragma unroll
    for (int o = 16; o; o >>= 1) sum += __shfl_xor_sync(0xffffffffu, sum, o);
    __syncthreads();
    if ((tid & 31) == 0) sred[tid >> 5] = sum;
    __syncthreads();
    if (tid == 0) {
        float v = 0.f;
#pragma unroll
        for (int w = 0; w < 8; w++) v += sred[w];
        rsum[r] = v;
    }
}

// ---------------- attention GEMM: fp16 MMA, 128i x 128h, 3-stage pipeline --
// grid (16 i-tiles, 2 h-tiles, 8 b) = 256 blocks, occ 2 -> single wave.
// 3 stages: while computing tile T, loads T+1 and T+2 are in flight.
#define ATTN_SMEM_WORDS (6*128*AST + 128)
__global__ __launch_bounds__(256, 2)
void attn_mma(const __half* __restrict__ WhT, const __half* __restrict__ ws,
              const float* __restrict__ rsum, __half* __restrict__ go)
{
    extern __shared__ uint32_t dsm[];
    uint32_t* wsA[3] = { dsm, dsm + 128*AST, dsm + 2*128*AST };       // [i][j-half2]
    uint32_t* WhB[3] = { dsm + 3*128*AST, dsm + 4*128*AST, dsm + 5*128*AST }; // [h][j-half2]
    float* fis = (float*)(dsm + 6*128*AST);

    const int b = blockIdx.z, i0 = blockIdx.x * 128, h0 = blockIdx.y * 128;
    const int tid = threadIdx.x;
    const int warp = tid >> 5, lane = tid & 31;
    const int g = lane >> 2, t = lane & 3;
    const int wm = warp >> 2, wn = warp & 3;   // 2 i-warps x 4 h-warps

    const __half* WhT_b = WhT + (size_t)(b * HH + h0) * NN_;
    const __half* ws_b  = ws  + (size_t)(b * NN_ + i0) * NN_;

    if (tid < 128) fis[tid] = 1.0f / rsum[b * NN_ + i0 + tid];
    __syncthreads();

    auto issue = [&](int T, int st) {
        const __half* asrc = ws_b + T * 64;
#pragma unroll
        for (int s = 0; s < 4; s++) {            // 1024 cp16: 128i x 64j
            int idx = tid + 256 * s;
            int i = idx >> 3, grp = idx & 7;
            cp16(&wsA[st][i * AST + grp * 4], asrc + (size_t)i * NN_ + grp * 8);
        }
        const __half* wsrc = WhT_b + T * 64;
#pragma unroll
        for (int s = 0; s < 4; s++) {            // 1024 cp16: 128h x 64j
            int idx = tid + 256 * s;
            int h = idx >> 3, grp = idx & 7;
            cp16(&WhB[st][h * AST + grp * 4], wsrc + (size_t)h * NN_ + grp * 8);
        }
    };

    float acc[4][4][4] = {};
    const int NT = NN_ / 64;

    issue(0, 0); cp_commit();
    issue(1, 1); cp_commit();

    for (int T = 0; T < NT; T++) {
        const int st = T % 3;
        // ensure group T has landed: committed so far = min(T+1, NT-1)
        if (T + 1 < NT) cp_wait1(); else cp_wait0();
        __syncthreads();                         // also drains compute on stage (T+2)%3
        if (T + 2 < NT) { issue(T + 2, (T + 2) % 3); cp_commit(); }

#pragma unroll
        for (int ks = 0; ks < 4; ks++) {
            const int kk = ks * 8;
            uint32_t af[4][4], bf[4][2];
#pragma unroll
            for (int mf = 0; mf < 4; mf++) {
                int r0 = wm * 64 + mf * 16 + g;
                af[mf][0] = wsA[st][(r0    ) * AST + kk + t];
                af[mf][1] = wsA[st][(r0 + 8) * AST + kk + t];
                af[mf][2] = wsA[st][(r0    ) * AST + kk + t + 4];
                af[mf][3] = wsA[st][(r0 + 8) * AST + kk + t + 4];
            }
#pragma unroll
            for (int nf = 0; nf < 4; nf++) {
                int c0 = wn * 32 + nf * 8 + g;
                bf[nf][0] = WhB[st][c0 * AST + kk + t];
                bf[nf][1] = WhB[st][c0 * AST + kk + t + 4];
            }
#pragma unroll
            for (int mf = 0; mf < 4; mf++)
#pragma unroll
                for (int nf = 0; nf < 4; nf++)
                    mma_f16(acc[mf][nf], af[mf], bf[nf]);
        }
    }

#pragma unroll
    for (int mf = 0; mf < 4; mf++) {
        int il = wm * 64 + mf * 16 + g;
        float s0 = fis[il], s1 = fis[il + 8];
        __half* o0 = go + (size_t)(b * NN_ + i0 + il)     * HH + h0;
        __half* o1 = go + (size_t)(b * NN_ + i0 + il + 8) * HH + h0;
#pragma unroll
        for (int nf = 0; nf < 4; nf++) {
            int hc = wn * 32 + nf * 8 + 2 * t;
            *(__half2*)(o0 + hc) = __floats2half2_rn(acc[mf][nf][0] * s0, acc[mf][nf][1] * s0);
            *(__half2*)(o1 + hc) = __floats2half2_rn(acc[mf][nf][2] * s1, acc[mf][nf][3] * s1);
        }
    }
}

// ---------------- gh GEMM: fp16 MMA, 128m x 192n tiles, 2-stage ------------
#define GH_SMEM_BYTES (2 * (128 + 192) * AST * 4)
__global__ __launch_bounds__(256, 2)
void gh_gemm_f16(const __half* __restrict__ A16, const __half* __restrict__ B16,
                 const float* __restrict__ bias, __half* __restrict__ C16,
                 int N, int K)
{
    extern __shared__ uint32_t dsm[];
    uint32_t* As[2] = { dsm, dsm + 128 * AST };
    uint32_t* Bs[2] = { dsm + 2 * 128 * AST, dsm + 2 * 128 * AST + 192 * AST };

    const int tid  = threadIdx.x;
    const int warp = tid >> 5, lane = tid & 31;
    const int g = lane >> 2, t = lane & 3;
    const int wm = warp & 1, wn = warp >> 1;   // 2 m x 4 n (48 cols each)
    const int m0 = blockIdx.y * 128, n0 = blockIdx.x * 192;
    const int KT = K / 64;

    auto issue = [&](int T, int st) {
#pragma unroll
        for (int s = 0; s < 4; s++) {
            int f = tid + 256 * s;
            int m = f >> 3, grp = f & 7;
            cp16(&As[st][m * AST + grp * 4], A16 + (size_t)(m0 + m) * K + T * 64 + grp * 8);
        }
#pragma unroll
        for (int s = 0; s < 6; s++) {
            int f = tid + 256 * s;             // 1536 cp16: 192n x 64k
            int n = f >> 3, grp = f & 7;
            cp16(&Bs[st][n * AST + grp * 4], B16 + (size_t)(n0 + n) * K + T * 64 + grp * 8);
        }
    };

    float acc[4][6][4] = {};

    issue(0, 0); cp_commit();

    for (int T = 0; T < KT; T++) {
        const int st = T & 1;
        if (T + 1 < KT) { issue(T + 1, st ^ 1); cp_commit(); cp_wait1(); }
        else            { cp_wait0(); }
        __syncthreads();

#pragma unroll
        for (int ks = 0; ks < 4; ks++) {
            const int kk = ks * 8;
            uint32_t af[4][4], bf[6][2];
#pragma unroll
            for (int mf = 0; mf < 4; mf++) {
                int r0 = wm * 64 + mf * 16 + g;
                af[mf][0] = As[st][(r0    ) * AST + kk + t];
                af[mf][1] = As[st][(r0 + 8) * AST + kk + t];
                af[mf][2] = As[st][(r0    ) * AST + kk + t + 4];
                af[mf][3] = As[st][(r0 + 8) * AST + kk + t + 4];
            }
#pragma unroll
            for (int nf = 0; nf < 6; nf++) {
                int c0 = wn * 48 + nf * 8 + g;
                bf[nf][0] = Bs[st][c0 * AST + kk + t];
                bf[nf][1] = Bs[st][c0 * AST + kk + t + 4];
            }
#pragma unroll
            for (int mf = 0; mf < 4; mf++)
#pragma unroll
                for (int nf = 0; nf < 6; nf++)
                    mma_f16(acc[mf][nf], af[mf], bf[nf]);
        }
        __syncthreads();
    }

#pragma unroll
    for (int mf = 0; mf < 4; mf++) {
        int row = m0 + wm * 64 + mf * 16 + g;
#pragma unroll
        for (int nf = 0; nf < 6; nf++) {
            int col = n0 + wn * 48 + nf * 8 + 2 * t;
            float b0v = bias[col], b1v = bias[col + 1];
            *(__half2*)(C16 + (size_t)row * N + col) =
                __floats2half2_rn(acc[mf][nf][0] + b0v, acc[mf][nf][1] + b1v);
            *(__half2*)(C16 + (size_t)(row + 8) * N + col) =
                __floats2half2_rn(acc[mf][nf][2] + b0v, acc[mf][nf][3] + b1v);
        }
    }
}

// ---------------- fused gi GEMM (fp16, 3 gates) + GRU, 2-stage -------------
#define GRU_SMEM_BYTES ((2*128*AST + 2*3*32*AST) * 4)
__global__ __launch_bounds__(256, 2)
void gru_gemm(const __half* __restrict__ go, const __half* __restrict__ wih,
              const float* __restrict__ b_ih, const __half* __restrict__ gh,
              const float* __restrict__ x, float* __restrict__ out)
{
    extern __shared__ uint32_t dsm[];
    uint32_t* As[2] = { dsm, dsm + 128 * AST };
    uint32_t* Bbase  = dsm + 2 * 128 * AST;   // [st][gate][32*AST]

    const int tid  = threadIdx.x;
    const int warp = tid >> 5, lane = tid & 31;
    const int g = lane >> 2, t = lane & 3;
    const int wm = warp >> 1, wn = warp & 1;  // 4 m-warps x 2 n-warps
    const int m0 = blockIdx.y * 128;
    const int h0 = blockIdx.x * 32;

    auto issue = [&](int T, int st) {
#pragma unroll
        for (int s = 0; s < 4; s++) {
            int f = tid + 256 * s;
            int m = f >> 3, grp = f & 7;
            cp16(&As[st][m * AST + grp * 4], go + (size_t)(m0 + m) * HH + T * 64 + grp * 8);
        }
        uint32_t* Bst = Bbase + st * 3 * 32 * AST;
#pragma unroll
        for (int s = 0; s < 3; s++) {
            int idx = tid + 256 * s;            // 0..767
            int gate = idx >> 8;
            int r = idx & 255;
            int n = r >> 3, grp = r & 7;
            cp16(&Bst[gate * 32 * AST + n * AST + grp * 4],
                 wih + (size_t)(gate * HH + h0 + n) * HH + T * 64 + grp * 8);
        }
    };

    float acc[3][2][2][4] = {};

    issue(0, 0); cp_commit();

    for (int T = 0; T < 4; T++) {
        const int st = T & 1;
        if (T + 1 < 4) { issue(T + 1, st ^ 1); cp_commit(); cp_wait1(); }
        else           { cp_wait0(); }
        __syncthreads();
        uint32_t* Bst = Bbase + st * 3 * 32 * AST;

#pragma unroll
        for (int ks = 0; ks < 4; ks++) {
            const int kk = ks * 8;
            uint32_t af[2][4], bf[3][2][2];
#pragma unroll
            for (int mf = 0; mf < 2; mf++) {
                int r0 = wm * 32 + mf * 16 + g;
                af[mf][0] = As[st][(r0    ) * AST + kk + t];
                af[mf][1] = As[st][(r0 + 8) * AST + kk + t];
                af[mf][2] = As[st][(r0    ) * AST + kk + t + 4];
                af[mf][3] = As[st][(r0 + 8) * AST + kk + t + 4];
            }
#pragma unroll
            for (int gate = 0; gate < 3; gate++)
#pragma unroll
                for (int nf = 0; nf < 2; nf++) {
                    int c0 = wn * 16 + nf * 8 + g;
                    bf[gate][nf][0] = Bst[gate * 32 * AST + c0 * AST + kk + t];
                    bf[gate][nf][1] = Bst[gate * 32 * AST + c0 * AST + kk + t + 4];
                }
#pragma unroll
            for (int gate = 0; gate < 3; gate++)
#pragma unroll
                for (int mf = 0; mf < 2; mf++)
#pragma unroll
                    for (int nf = 0; nf < 2; nf++)
                        mma_f16(acc[gate][mf][nf], af[mf], bf[gate][nf]);
        }
        __syncthreads();
    }

    // ---- GRU epilogue
#pragma unroll
    for (int mf = 0; mf < 2; mf++) {
#pragma unroll
        for (int nf = 0; nf < 2; nf++) {
            int col = h0 + wn * 16 + nf * 8 + 2 * t;
            float br0 = b_ih[col],            br1 = b_ih[col + 1];
            float bz0 = b_ih[HH + col],       bz1 = b_ih[HH + col + 1];
            float bn0 = b_ih[2 * HH + col],   bn1 = b_ih[2 * HH + col + 1];
#pragma unroll
            for (int pr = 0; pr < 2; pr++) {
                int row = m0 + wm * 32 + mf * 16 + g + pr * 8;
                const __half* ghr = gh + (size_t)row * (3 * HH);
                float2 hr = __half22float2(*(const __half2*)(ghr + col));
                float2 hz = __half22float2(*(const __half2*)(ghr + HH + col));
                float2 hn = __half22float2(*(const __half2*)(ghr + 2 * HH + col));
                float2 xv = *(const float2*)(x + (size_t)row * HH + col);

                float ir0 = acc[0][mf][nf][pr*2+0] + br0, ir1 = acc[0][mf][nf][pr*2+1] + br1;
                float iz0 = acc[1][mf][nf][pr*2+0] + bz0, iz1 = acc[1][mf][nf][pr*2+1] + bz1;
                float in0 = acc[2][mf][nf][pr*2+0] + bn0, in1 = acc[2][mf][nf][pr*2+1] + bn1;

                float r0g = 1.f / (1.f + __expf(-(ir0 + hr.x)));
                float r1g = 1.f / (1.f + __expf(-(ir1 + hr.y)));
                float z0g = 1.f / (1.f + __expf(-(iz0 + hz.x)));
                float z1g = 1.f / (1.f + __expf(-(iz1 + hz.y)));
                float n0g = tanhf(in0 + r0g * hn.x);
                float n1g = tanhf(in1 + r1g * hn.y);
                float2 o;
                o.x = (1.f - z0g) * n0g + z0g * xv.x;
                o.y = (1.f - z1g) * n1g + z1g * xv.y;
                *(float2*)(out + (size_t)row * HH + col) = o;
            }
        }
    }
}

// ---------------- launch ---------------------------------------------------
extern "C" void kernel_launch(void* const* d_in, const int* in_sizes, int n_in,
                              void* d_out, int out_size)
{
    const int*   adj  = (const int*)  d_in[0];
    const float* x    = (const float*)d_in[1];
    const float* W    = (const float*)d_in[2];
    const float* a    = (const float*)d_in[3];
    const float* w_ih = (const float*)d_in[4];
    const float* w_hh = (const float*)d_in[5];
    const float* b_ih = (const float*)d_in[6];
    const float* b_hh = (const float*)d_in[7];
    float* out = (float*)d_out;

    float *pWh1, *pWh2, *prs, *pav;
    __half *pWhT, *pws, *pgo16, *pgh16, *px16, *pwih16, *pwhh16, *pwt16;
    cudaGetSymbolAddress((void**)&pWhT,  g_WhT);
    cudaGetSymbolAddress((void**)&pws,   g_ws);
    cudaGetSymbolAddress((void**)&pgo16, g_go16);
    cudaGetSymbolAddress((void**)&pgh16, g_gh16);
    cudaGetSymbolAddress((void**)&px16,  g_x16);
    cudaGetSymbolAddress((void**)&pwih16, g_wih16);
    cudaGetSymbolAddress((void**)&pwhh16, g_whh16);
    cudaGetSymbolAddress((void**)&pwt16,  g_wt16);
    cudaGetSymbolAddress((void**)&pav,  g_av);
    cudaGetSymbolAddress((void**)&pWh1, g_Wh1);
    cudaGetSymbolAddress((void**)&pWh2, g_Wh2);
    cudaGetSymbolAddress((void**)&prs,  g_rs);

    cudaFuncSetAttribute(attn_mma, cudaFuncAttributeMaxDynamicSharedMemorySize,
                         ATTN_SMEM_WORDS * 4);
    cudaFuncSetAttribute(whT_f16, cudaFuncAttributeMaxDynamicSharedMemorySize,
                         WT_SMEM_BYTES);
    cudaFuncSetAttribute(gh_gemm_f16, cudaFuncAttributeMaxDynamicSharedMemorySize,
                         GH_SMEM_BYTES);
    cudaFuncSetAttribute(gru_gemm, cudaFuncAttributeMaxDynamicSharedMemorySize,
                         GRU_SMEM_BYTES);

    // 0) fp16 conversions (fused) + W transpose + av = W@a
    cvt_all<<<2240, 256>>>(x, px16, w_ih, pwih16, w_hh, pwhh16);
    cvt_wT<<<dim3(HH / 32, DD / 32), dim3(32, 8)>>>(W, pwt16);
    av_gemv<<<32, 256>>>(W, a, pav);

    // 1) Wh1/Wh2 = x16 @ av (associativity)
    wh12_x<<<ROWS / 8, 256>>>(px16, pav, pWh1, pWh2);

    // 2) adj -> softmax stats + fp16 ws (single adj pass)
    pack_stats<<<ROWS, 256>>>(adj, pWh1, pWh2, pws, prs);

    // 3) WhT = WT16 @ x16^T  (fp16 MMA, 2-stage)
    whT_f16<<<dim3(ROWS / 128, HH / 128), 256, WT_SMEM_BYTES>>>(pwt16, px16, pWhT);

    // 4) attention GEMM (fp16 MMA, 128x128, 3-stage pipeline) -> go16
    attn_mma<<<dim3(NN_ / 128, HH / 128, BB), 256, ATTN_SMEM_WORDS * 4>>>(
        pWhT, pws, prs, pgo16);

    // 5) gh16 = x16 @ w_hh16^T + b_hh (fp16 MMA, 192-wide tiles)
    gh_gemm_f16<<<dim3(3 * HH / 192, ROWS / 128), 256, GH_SMEM_BYTES>>>(
        px16, pwhh16, b_hh, pgh16, 3 * HH, HH);

    // 6) gi GEMM (fp16, 3 gates) + GRU fused -> out (2-stage, fp32 x epilogue)
    gru_gemm<<<dim3(HH / 32, ROWS / 128), 256, GRU_SMEM_BYTES>>>(
        pgo16, pwih16, b_ih, pgh16, x, out);
}

// round 16
// speedup vs baseline: 1.0615x; 1.0615x over previous
#include <cuda_runtime.h>
#include <cuda_fp16.h>
#include <cstdint>
#include <math.h>

// Problem constants
#define BB 8
#define NN_ 2048
#define DD 256
#define HH 256
#define ROWS (BB*NN_)          // 16384
#define ALPHA 0.2f

// ---------------- scratch (device globals) ---------------------------------
__device__ __half   g_WhT [(size_t)ROWS*HH];     // fp16 Wh^T [b][h][i]
__device__ __half   g_ws  [(size_t)ROWS*NN_];    // fp16 attention weights [r][j]
__device__ __half   g_go16[(size_t)ROWS*HH];     // fp16 graph_out
__device__ __half   g_gh16[(size_t)ROWS*3*HH];   // fp16 gh
__device__ __half   g_x16 [(size_t)ROWS*HH];     // fp16 x
__device__ __half   g_wih16[3*HH*HH];
__device__ __half   g_whh16[3*HH*HH];
__device__ __half   g_wt16[HH*DD];               // fp16 W^T [h][d]
__device__ float    g_av [2*DD];                 // W@a1 | W@a2
__device__ float    g_Wh1[ROWS];
__device__ float    g_Wh2[ROWS];
__device__ float    g_rs [ROWS];

// ---------------- helpers ---------------------------------------------------
__device__ __forceinline__ void mma_f16(float* d, const uint32_t* a, const uint32_t* b) {
    asm volatile("mma.sync.aligned.m16n8k16.row.col.f32.f16.f16.f32 "
        "{%0,%1,%2,%3}, {%4,%5,%6,%7}, {%8,%9}, {%0,%1,%2,%3};\n"
        : "+f"(d[0]), "+f"(d[1]), "+f"(d[2]), "+f"(d[3])
        : "r"(a[0]), "r"(a[1]), "r"(a[2]), "r"(a[3]), "r"(b[0]), "r"(b[1]));
}
__device__ __forceinline__ void cp16(void* smem, const void* gmem) {
    uint32_t s = (uint32_t)__cvta_generic_to_shared(smem);
    asm volatile("cp.async.cg.shared.global [%0], [%1], 16;\n" :: "r"(s), "l"(gmem));
}
__device__ __forceinline__ void cp_commit() { asm volatile("cp.async.commit_group;\n" ::: "memory"); }
__device__ __forceinline__ void cp_wait0()  { asm volatile("cp.async.wait_group 0;\n" ::: "memory"); }
__device__ __forceinline__ void cp_wait1()  { asm volatile("cp.async.wait_group 1;\n" ::: "memory"); }

#define AST 36     // [row][k-word] stride: frag LDS bank = (4g+t)%32, conflict-free

// ---------------- fused fp32 -> fp16 converter (x, w_ih, w_hh in one) ------
__global__ __launch_bounds__(256)
void cvt_all(const float* __restrict__ x,  __half* __restrict__ x16,
             const float* __restrict__ wi, __half* __restrict__ wi16,
             const float* __restrict__ wh, __half* __restrict__ wh16)
{
    int bid = blockIdx.x;
    const float* src; __half* dst; int base;
    if (bid < 2048)      { src = x;  dst = x16;  base = bid * 2048; }
    else if (bid < 2144) { src = wi; dst = wi16; base = (bid - 2048) * 2048; }
    else                 { src = wh; dst = wh16; base = (bid - 2144) * 2048; }
    int i = base + threadIdx.x * 8;
    float4 v0 = *(const float4*)(src + i);
    float4 v1 = *(const float4*)(src + i + 4);
    __half2 h[4] = { __floats2half2_rn(v0.x, v0.y), __floats2half2_rn(v0.z, v0.w),
                     __floats2half2_rn(v1.x, v1.y), __floats2half2_rn(v1.z, v1.w) };
    *(uint4*)(dst + i) = *(uint4*)h;
}

// ---------------- W[d][h] -> WT16[h][d] fp16 transpose ---------------------
__global__ void cvt_wT(const float* __restrict__ W, __half* __restrict__ WT)
{
    __shared__ float tle[32][33];
    const int h0 = blockIdx.x * 32, d0 = blockIdx.y * 32;
    const int tx = threadIdx.x, ty = threadIdx.y;    // 32 x 8
#pragma unroll
    for (int k = 0; k < 4; k++)
        tle[ty + 8 * k][tx] = W[(size_t)(d0 + ty + 8 * k) * HH + h0 + tx];
    __syncthreads();
#pragma unroll
    for (int k = 0; k < 4; k++)
        WT[(size_t)(h0 + ty + 8 * k) * DD + d0 + tx] = __float2half(tle[tx][ty + 8 * k]);
}

// ---------------- av = [W@a1 | W@a2]  (tiny fp32 GEMV) ---------------------
__global__ __launch_bounds__(256)
void av_gemv(const float* __restrict__ W, const float* __restrict__ a,
             float* __restrict__ av)
{
    const int warp = threadIdx.x >> 5, lane = threadIdx.x & 31;
    const int d = blockIdx.x * 8 + warp;           // 0..255
    const float* wr = W + (size_t)d * HH + lane * 8;
    float4 w0 = *(const float4*)wr;
    float4 w1 = *(const float4*)(wr + 4);
    const float* a1 = a + lane * 8;
    const float* a2 = a + HH + lane * 8;
    float4 p0 = *(const float4*)a1, p1 = *(const float4*)(a1 + 4);
    float4 q0 = *(const float4*)a2, q1 = *(const float4*)(a2 + 4);
    float s1 = w0.x*p0.x + w0.y*p0.y + w0.z*p0.z + w0.w*p0.w
             + w1.x*p1.x + w1.y*p1.y + w1.z*p1.z + w1.w*p1.w;
    float s2 = w0.x*q0.x + w0.y*q0.y + w0.z*q0.z + w0.w*q0.w
             + w1.x*q1.x + w1.y*q1.y + w1.z*q1.z + w1.w*q1.w;
#pragma unroll
    for (int o = 16; o; o >>= 1) {
        s1 += __shfl_xor_sync(0xffffffffu, s1, o);
        s2 += __shfl_xor_sync(0xffffffffu, s2, o);
    }
    if (lane == 0) { av[d] = s1; av[DD + d] = s2; }
}

// ---------------- Wh1/Wh2 via associativity: Wh1 = x16 . av1 ---------------
__global__ __launch_bounds__(256)
void wh12_x(const __half* __restrict__ x16, const float* __restrict__ av,
            float* __restrict__ Wh1, float* __restrict__ Wh2)
{
    const int warp = threadIdx.x >> 5, lane = threadIdx.x & 31;
    const int r = blockIdx.x * 8 + warp;
    const __half* xr = x16 + (size_t)r * DD + lane * 8;
    uint4 xv = *(const uint4*)xr;                  // 8 halves
    const __half2* xh = (const __half2*)&xv;
    const float* a1 = av + lane * 8;
    const float* a2 = av + DD + lane * 8;
    float4 p0 = *(const float4*)a1, p1 = *(const float4*)(a1 + 4);
    float4 q0 = *(const float4*)a2, q1 = *(const float4*)(a2 + 4);
    float2 x0 = __half22float2(xh[0]);
    float2 x1 = __half22float2(xh[1]);
    float2 x2 = __half22float2(xh[2]);
    float2 x3 = __half22float2(xh[3]);
    float s1 = x0.x*p0.x + x0.y*p0.y + x1.x*p0.z + x1.y*p0.w
             + x2.x*p1.x + x2.y*p1.y + x3.x*p1.z + x3.y*p1.w;
    float s2 = x0.x*q0.x + x0.y*q0.y + x1.x*q0.z + x1.y*q0.w
             + x2.x*q1.x + x2.y*q1.y + x3.x*q1.z + x3.y*q1.w;
#pragma unroll
    for (int o = 16; o; o >>= 1) {
        s1 += __shfl_xor_sync(0xffffffffu, s1, o);
        s2 += __shfl_xor_sync(0xffffffffu, s2, o);
    }
    if (lane == 0) { Wh1[r] = s1; Wh2[r] = s2; }
}

// ---------------- whT GEMM: WhT[b][h][i] = WT16 @ x16^T (fp16 MMA) ---------
#define WT_SMEM_BYTES (4 * 128 * AST * 4)
__global__ __launch_bounds__(256, 2)
void whT_f16(const __half* __restrict__ WT16, const __half* __restrict__ x16,
             __half* __restrict__ WhT)
{
    extern __shared__ uint32_t dsm[];
    uint32_t* As[2] = { dsm, dsm + 128 * AST };
    uint32_t* Bs[2] = { dsm + 2 * 128 * AST, dsm + 3 * 128 * AST };

    const int tid  = threadIdx.x;
    const int warp = tid >> 5, lane = tid & 31;
    const int g = lane >> 2, t = lane & 3;
    const int wm = warp & 1, wn = warp >> 1;   // 2 m x 4 n
    const int m0 = blockIdx.y * 128;           // h block
    const int n0 = blockIdx.x * 128;           // global row block
    const int b  = n0 >> 11;
    const int ib = n0 & (NN_ - 1);

    auto issue = [&](int T, int st) {
#pragma unroll
        for (int s = 0; s < 4; s++) {
            int f = tid + 256 * s;
            int m = f >> 3, grp = f & 7;
            cp16(&As[st][m * AST + grp * 4], WT16 + (size_t)(m0 + m) * DD + T * 64 + grp * 8);
        }
#pragma unroll
        for (int s = 0; s < 4; s++) {
            int f = tid + 256 * s;
            int n = f >> 3, grp = f & 7;
            cp16(&Bs[st][n * AST + grp * 4], x16 + (size_t)(n0 + n) * DD + T * 64 + grp * 8);
        }
    };

    float acc[4][4][4] = {};

    issue(0, 0); cp_commit();

    for (int T = 0; T < 4; T++) {
        const int st = T & 1;
        if (T + 1 < 4) { issue(T + 1, st ^ 1); cp_commit(); cp_wait1(); }
        else           { cp_wait0(); }
        __syncthreads();

#pragma unroll
        for (int ks = 0; ks < 4; ks++) {
            const int kk = ks * 8;
            uint32_t af[4][4], bf[4][2];
#pragma unroll
            for (int mf = 0; mf < 4; mf++) {
                int r0 = wm * 64 + mf * 16 + g;
                af[mf][0] = As[st][(r0    ) * AST + kk + t];
                af[mf][1] = As[st][(r0 + 8) * AST + kk + t];
                af[mf][2] = As[st][(r0    ) * AST + kk + t + 4];
                af[mf][3] = As[st][(r0 + 8) * AST + kk + t + 4];
            }
#pragma unroll
            for (int nf = 0; nf < 4; nf++) {
                int c0 = wn * 32 + nf * 8 + g;
                bf[nf][0] = Bs[st][c0 * AST + kk + t];
                bf[nf][1] = Bs[st][c0 * AST + kk + t + 4];
            }
#pragma unroll
            for (int mf = 0; mf < 4; mf++)
#pragma unroll
                for (int nf = 0; nf < 4; nf++)
                    mma_f16(acc[mf][nf], af[mf], bf[nf]);
        }
        __syncthreads();
    }

#pragma unroll
    for (int mf = 0; mf < 4; mf++) {
        int h = m0 + wm * 64 + mf * 16 + g;
#pragma unroll
        for (int nf = 0; nf < 4; nf++) {
            int i = ib + wn * 32 + nf * 8 + 2 * t;
            *(__half2*)(WhT + (size_t)(b * HH + h)     * NN_ + i) =
                __floats2half2_rn(acc[mf][nf][0], acc[mf][nf][1]);
            *(__half2*)(WhT + (size_t)(b * HH + h + 8) * NN_ + i) =
                __floats2half2_rn(acc[mf][nf][2], acc[mf][nf][3]);
        }
    }
}

// ---------------- fused: adj -> masked softmax stats + fp16 ws matrix ------
__global__ __launch_bounds__(256)
void pack_stats(const int* __restrict__ adj, const float* __restrict__ Wh1,
                const float* __restrict__ Wh2, __half* __restrict__ ws,
                float* __restrict__ rsum)
{
    const int r = blockIdx.x;
    const int b = r >> 11;
    const int tid = threadIdx.x;
    const float w1 = Wh1[r];
    const float* Wh2b = Wh2 + (b << 11);

    const int4* ap = (const int4*)(adj + (size_t)r * NN_ + tid * 8);
    int4 a0 = ap[0], a1 = ap[1];
    float4 w0 = *(const float4*)(Wh2b + tid * 8);
    float4 w1v = *(const float4*)(Wh2b + tid * 8 + 4);

    int m[8] = { a0.x > 0, a0.y > 0, a0.z > 0, a0.w > 0,
                 a1.x > 0, a1.y > 0, a1.z > 0, a1.w > 0 };
    float wv[8] = { w0.x, w0.y, w0.z, w0.w, w1v.x, w1v.y, w1v.z, w1v.w };

    float lrv[8];
    float mx = -INFINITY;
#pragma unroll
    for (int k = 0; k < 8; k++) {
        float sv = w1 + wv[k];
        float lr = sv > 0.f ? sv : ALPHA * sv;
        lrv[k] = m[k] ? lr : -INFINITY;
        mx = fmaxf(mx, lrv[k]);
    }

    __shared__ float sred[8];
#pragma unroll
    for (int o = 16; o; o >>= 1) mx = fmaxf(mx, __shfl_xor_sync(0xffffffffu, mx, o));
    if ((tid & 31) == 0) sred[tid >> 5] = mx;
    __syncthreads();
    if (tid == 0) {
        float v = sred[0];
#pragma unroll
        for (int w = 1; w < 8; w++) v = fmaxf(v, sred[w]);
        sred[0] = v;
    }
    __syncthreads();
    mx = sred[0];

    float ev[8];
    float sum = 0.f;
#pragma unroll
    for (int k = 0; k < 8; k++) { ev[k] = __expf(lrv[k] - mx); sum += ev[k]; }
    __half2 hq[4];
#pragma unroll
    for (int k = 0; k < 4; k++) hq[k] = __floats2half2_rn(ev[2*k], ev[2*k+1]);
    *(uint4*)(ws + (size_t)r * NN_ + tid * 8) = *(uint4*)hq;

#pragma unroll
    for (int o = 16; o; o >>= 1) sum += __shfl_xor_sync(0xffffffffu, sum, o);
    __syncthreads();
    if ((tid & 31) == 0) sred[tid >> 5] = sum;
    __syncthreads();
    if (tid == 0) {
        float v = 0.f;
#pragma unroll
        for (int w = 0; w < 8; w++) v += sred[w];
        rsum[r] = v;
    }
}

// ---------------- attention GEMM: fp16 MMA, 128i x 128h, 2-stage (R13) -----
#define ATTN_SMEM_WORDS (4*128*AST + 128)
__global__ __launch_bounds__(256, 2)
void attn_mma(const __half* __restrict__ WhT, const __half* __restrict__ ws,
              const float* __restrict__ rsum, __half* __restrict__ go)
{
    extern __shared__ uint32_t dsm[];
    uint32_t* wsA[2] = { dsm, dsm + 128 * AST };                      // [i][j-half2]
    uint32_t* WhB[2] = { dsm + 2*128*AST, dsm + 3*128*AST };          // [h][j-half2]
    float* fis = (float*)(dsm + 4*128*AST);

    const int b = blockIdx.z, i0 = blockIdx.x * 128, h0 = blockIdx.y * 128;
    const int tid = threadIdx.x;
    const int warp = tid >> 5, lane = tid & 31;
    const int g = lane >> 2, t = lane & 3;
    const int wm = warp >> 2, wn = warp & 3;   // 2 i-warps x 4 h-warps

    const __half* WhT_b = WhT + (size_t)(b * HH + h0) * NN_;
    const __half* ws_b  = ws  + (size_t)(b * NN_ + i0) * NN_;

    if (tid < 128) fis[tid] = 1.0f / rsum[b * NN_ + i0 + tid];
    __syncthreads();

    auto issue = [&](int T, int st) {
        const __half* asrc = ws_b + T * 64;
#pragma unroll
        for (int s = 0; s < 4; s++) {            // 1024 cp16: 128i x 64j
            int idx = tid + 256 * s;
            int i = idx >> 3, grp = idx & 7;
            cp16(&wsA[st][i * AST + grp * 4], asrc + (size_t)i * NN_ + grp * 8);
        }
        const __half* wsrc = WhT_b + T * 64;
#pragma unroll
        for (int s = 0; s < 4; s++) {            // 1024 cp16: 128h x 64j
            int idx = tid + 256 * s;
            int h = idx >> 3, grp = idx & 7;
            cp16(&WhB[st][h * AST + grp * 4], wsrc + (size_t)h * NN_ + grp * 8);
        }
    };

    float acc[4][4][4] = {};

    issue(0, 0); cp_commit(); cp_wait0(); __syncthreads();

    for (int T = 0; T < NN_ / 64; T++) {
        const int st = T & 1, nst = st ^ 1;
        if (T + 1 < NN_ / 64) issue(T + 1, nst);
        cp_commit();

#pragma unroll
        for (int ks = 0; ks < 4; ks++) {
            const int kk = ks * 8;
            uint32_t af[4][4], bf[4][2];
#pragma unroll
            for (int mf = 0; mf < 4; mf++) {
                int r0 = wm * 64 + mf * 16 + g;
                af[mf][0] = wsA[st][(r0    ) * AST + kk + t];
                af[mf][1] = wsA[st][(r0 + 8) * AST + kk + t];
                af[mf][2] = wsA[st][(r0    ) * AST + kk + t + 4];
                af[mf][3] = wsA[st][(r0 + 8) * AST + kk + t + 4];
            }
#pragma unroll
            for (int nf = 0; nf < 4; nf++) {
                int c0 = wn * 32 + nf * 8 + g;
                bf[nf][0] = WhB[st][c0 * AST + kk + t];
                bf[nf][1] = WhB[st][c0 * AST + kk + t + 4];
            }
#pragma unroll
            for (int mf = 0; mf < 4; mf++)
#pragma unroll
                for (int nf = 0; nf < 4; nf++)
                    mma_f16(acc[mf][nf], af[mf], bf[nf]);
        }
        cp_wait0(); __syncthreads();
    }

#pragma unroll
    for (int mf = 0; mf < 4; mf++) {
        int il = wm * 64 + mf * 16 + g;
        float s0 = fis[il], s1 = fis[il + 8];
        __half* o0 = go + (size_t)(b * NN_ + i0 + il)     * HH + h0;
        __half* o1 = go + (size_t)(b * NN_ + i0 + il + 8) * HH + h0;
#pragma unroll
        for (int nf = 0; nf < 4; nf++) {
            int hc = wn * 32 + nf * 8 + 2 * t;
            *(__half2*)(o0 + hc) = __floats2half2_rn(acc[mf][nf][0] * s0, acc[mf][nf][1] * s0);
            *(__half2*)(o1 + hc) = __floats2half2_rn(acc[mf][nf][2] * s1, acc[mf][nf][3] * s1);
        }
    }
}

// ---------------- gh GEMM: fp16 MMA, 128m x 192n tiles, 2-stage ------------
#define GH_SMEM_BYTES (2 * (128 + 192) * AST * 4)
__global__ __launch_bounds__(256, 2)
void gh_gemm_f16(const __half* __restrict__ A16, const __half* __restrict__ B16,
                 const float* __restrict__ bias, __half* __restrict__ C16,
                 int N, int K)
{
    extern __shared__ uint32_t dsm[];
    uint32_t* As[2] = { dsm, dsm + 128 * AST };
    uint32_t* Bs[2] = { dsm + 2 * 128 * AST, dsm + 2 * 128 * AST + 192 * AST };

    const int tid  = threadIdx.x;
    const int warp = tid >> 5, lane = tid & 31;
    const int g = lane >> 2, t = lane & 3;
    const int wm = warp & 1, wn = warp >> 1;   // 2 m x 4 n (48 cols each)
    const int m0 = blockIdx.y * 128, n0 = blockIdx.x * 192;
    const int KT = K / 64;

    auto issue = [&](int T, int st) {
#pragma unroll
        for (int s = 0; s < 4; s++) {
            int f = tid + 256 * s;
            int m = f >> 3, grp = f & 7;
            cp16(&As[st][m * AST + grp * 4], A16 + (size_t)(m0 + m) * K + T * 64 + grp * 8);
        }
#pragma unroll
        for (int s = 0; s < 6; s++) {
            int f = tid + 256 * s;             // 1536 cp16: 192n x 64k
            int n = f >> 3, grp = f & 7;
            cp16(&Bs[st][n * AST + grp * 4], B16 + (size_t)(n0 + n) * K + T * 64 + grp * 8);
        }
    };

    float acc[4][6][4] = {};

    issue(0, 0); cp_commit();

    for (int T = 0; T < KT; T++) {
        const int st = T & 1;
        if (T + 1 < KT) { issue(T + 1, st ^ 1); cp_commit(); cp_wait1(); }
        else            { cp_wait0(); }
        __syncthreads();

#pragma unroll
        for (int ks = 0; ks < 4; ks++) {
            const int kk = ks * 8;
            uint32_t af[4][4], bf[6][2];
#pragma unroll
            for (int mf = 0; mf < 4; mf++) {
                int r0 = wm * 64 + mf * 16 + g;
                af[mf][0] = As[st][(r0    ) * AST + kk + t];
                af[mf][1] = As[st][(r0 + 8) * AST + kk + t];
                af[mf][2] = As[st][(r0    ) * AST + kk + t + 4];
                af[mf][3] = As[st][(r0 + 8) * AST + kk + t + 4];
            }
#pragma unroll
            for (int nf = 0; nf < 6; nf++) {
                int c0 = wn * 48 + nf * 8 + g;
                bf[nf][0] = Bs[st][c0 * AST + kk + t];
                bf[nf][1] = Bs[st][c0 * AST + kk + t + 4];
            }
#pragma unroll
            for (int mf = 0; mf < 4; mf++)
#pragma unroll
                for (int nf = 0; nf < 6; nf++)
                    mma_f16(acc[mf][nf], af[mf], bf[nf]);
        }
        __syncthreads();
    }

#pragma unroll
    for (int mf = 0; mf < 4; mf++) {
        int row = m0 + wm * 64 + mf * 16 + g;
#pragma unroll
        for (int nf = 0; nf < 6; nf++) {
            int col = n0 + wn * 48 + nf * 8 + 2 * t;
            float b0v = bias[col], b1v = bias[col + 1];
            *(__half2*)(C16 + (size_t)row * N + col) =
                __floats2half2_rn(acc[mf][nf][0] + b0v, acc[mf][nf][1] + b1v);
            *(__half2*)(C16 + (size_t)(row + 8) * N + col) =
                __floats2half2_rn(acc[mf][nf][2] + b0v, acc[mf][nf][3] + b1v);
        }
    }
}

// ---------------- fused gi GEMM (fp16, 3 gates) + GRU, 2-stage -------------
#define GRU_SMEM_BYTES ((2*128*AST + 2*3*32*AST) * 4)
__global__ __launch_bounds__(256, 2)
void gru_gemm(const __half* __restrict__ go, const __half* __restrict__ wih,
              const float* __restrict__ b_ih, const __half* __restrict__ gh,
              const float* __restrict__ x, float* __restrict__ out)
{
    extern __shared__ uint32_t dsm[];
    uint32_t* As[2] = { dsm, dsm + 128 * AST };
    uint32_t* Bbase  = dsm + 2 * 128 * AST;   // [st][gate][32*AST]

    const int tid  = threadIdx.x;
    const int warp = tid >> 5, lane = tid & 31;
    const int g = lane >> 2, t = lane & 3;
    const int wm = warp >> 1, wn = warp & 1;  // 4 m-warps x 2 n-warps
    const int m0 = blockIdx.y * 128;
    const int h0 = blockIdx.x * 32;

    auto issue = [&](int T, int st) {
#pragma unroll
        for (int s = 0; s < 4; s++) {
            int f = tid + 256 * s;
            int m = f >> 3, grp = f & 7;
            cp16(&As[st][m * AST + grp * 4], go + (size_t)(m0 + m) * HH + T * 64 + grp * 8);
        }
        uint32_t* Bst = Bbase + st * 3 * 32 * AST;
#pragma unroll
        for (int s = 0; s < 3; s++) {
            int idx = tid + 256 * s;            // 0..767
            int gate = idx >> 8;
            int r = idx & 255;
            int n = r >> 3, grp = r & 7;
            cp16(&Bst[gate * 32 * AST + n * AST + grp * 4],
                 wih + (size_t)(gate * HH + h0 + n) * HH + T * 64 + grp * 8);
        }
    };

    float acc[3][2][2][4] = {};

    issue(0, 0); cp_commit();

    for (int T = 0; T < 4; T++) {
        const int st = T & 1;
        if (T + 1 < 4) { issue(T + 1, st ^ 1); cp_commit(); cp_wait1(); }
        else           { cp_wait0(); }
        __syncthreads();
        uint32_t* Bst = Bbase + st * 3 * 32 * AST;

#pragma unroll
        for (int ks = 0; ks < 4; ks++) {
            const int kk = ks * 8;
            uint32_t af[2][4], bf[3][2][2];
#pragma unroll
            for (int mf = 0; mf < 2; mf++) {
                int r0 = wm * 32 + mf * 16 + g;
                af[mf][0] = As[st][(r0    ) * AST + kk + t];
                af[mf][1] = As[st][(r0 + 8) * AST + kk + t];
                af[mf][2] = As[st][(r0    ) * AST + kk + t + 4];
                af[mf][3] = As[st][(r0 + 8) * AST + kk + t + 4];
            }
#pragma unroll
            for (int gate = 0; gate < 3; gate++)
#pragma unroll
                for (int nf = 0; nf < 2; nf++) {
                    int c0 = wn * 16 + nf * 8 + g;
                    bf[gate][nf][0] = Bst[gate * 32 * AST + c0 * AST + kk + t];
                    bf[gate][nf][1] = Bst[gate * 32 * AST + c0 * AST + kk + t + 4];
                }
#pragma unroll
            for (int gate = 0; gate < 3; gate++)
#pragma unroll
                for (int mf = 0; mf < 2; mf++)
#pragma unroll
                    for (int nf = 0; nf < 2; nf++)
                        mma_f16(acc[gate][mf][nf], af[mf], bf[gate][nf]);
        }
        __syncthreads();
    }

    // ---- GRU epilogue
#pragma unroll
    for (int mf = 0; mf < 2; mf++) {
#pragma unroll
        for (int nf = 0; nf < 2; nf++) {
            int col = h0 + wn * 16 + nf * 8 + 2 * t;
            float br0 = b_ih[col],            br1 = b_ih[col + 1];
            float bz0 = b_ih[HH + col],       bz1 = b_ih[HH + col + 1];
            float bn0 = b_ih[2 * HH + col],   bn1 = b_ih[2 * HH + col + 1];
#pragma unroll
            for (int pr = 0; pr < 2; pr++) {
                int row = m0 + wm * 32 + mf * 16 + g + pr * 8;
                const __half* ghr = gh + (size_t)row * (3 * HH);
                float2 hr = __half22float2(*(const __half2*)(ghr + col));
                float2 hz = __half22float2(*(const __half2*)(ghr + HH + col));
                float2 hn = __half22float2(*(const __half2*)(ghr + 2 * HH + col));
                float2 xv = *(const float2*)(x + (size_t)row * HH + col);

                float ir0 = acc[0][mf][nf][pr*2+0] + br0, ir1 = acc[0][mf][nf][pr*2+1] + br1;
                float iz0 = acc[1][mf][nf][pr*2+0] + bz0, iz1 = acc[1][mf][nf][pr*2+1] + bz1;
                float in0 = acc[2][mf][nf][pr*2+0] + bn0, in1 = acc[2][mf][nf][pr*2+1] + bn1;

                float r0g = 1.f / (1.f + __expf(-(ir0 + hr.x)));
                float r1g = 1.f / (1.f + __expf(-(ir1 + hr.y)));
                float z0g = 1.f / (1.f + __expf(-(iz0 + hz.x)));
                float z1g = 1.f / (1.f + __expf(-(iz1 + hz.y)));
                float n0g = tanhf(in0 + r0g * hn.x);
                float n1g = tanhf(in1 + r1g * hn.y);
                float2 o;
                o.x = (1.f - z0g) * n0g + z0g * xv.x;
                o.y = (1.f - z1g) * n1g + z1g * xv.y;
                *(float2*)(out + (size_t)row * HH + col) = o;
            }
        }
    }
}

// ---------------- launch: dual-stream fork/join ----------------------------
extern "C" void kernel_launch(void* const* d_in, const int* in_sizes, int n_in,
                              void* d_out, int out_size)
{
    const int*   adj  = (const int*)  d_in[0];
    const float* x    = (const float*)d_in[1];
    const float* W    = (const float*)d_in[2];
    const float* a    = (const float*)d_in[3];
    const float* w_ih = (const float*)d_in[4];
    const float* w_hh = (const float*)d_in[5];
    const float* b_ih = (const float*)d_in[6];
    const float* b_hh = (const float*)d_in[7];
    float* out = (float*)d_out;

    float *pWh1, *pWh2, *prs, *pav;
    __half *pWhT, *pws, *pgo16, *pgh16, *px16, *pwih16, *pwhh16, *pwt16;
    cudaGetSymbolAddress((void**)&pWhT,  g_WhT);
    cudaGetSymbolAddress((void**)&pws,   g_ws);
    cudaGetSymbolAddress((void**)&pgo16, g_go16);
    cudaGetSymbolAddress((void**)&pgh16, g_gh16);
    cudaGetSymbolAddress((void**)&px16,  g_x16);
    cudaGetSymbolAddress((void**)&pwih16, g_wih16);
    cudaGetSymbolAddress((void**)&pwhh16, g_whh16);
    cudaGetSymbolAddress((void**)&pwt16,  g_wt16);
    cudaGetSymbolAddress((void**)&pav,  g_av);
    cudaGetSymbolAddress((void**)&pWh1, g_Wh1);
    cudaGetSymbolAddress((void**)&pWh2, g_Wh2);
    cudaGetSymbolAddress((void**)&prs,  g_rs);

    // One-time resources (created on the first, non-captured correctness call)
    static cudaStream_t s1 = nullptr;
    static cudaEvent_t evX = nullptr, evWhT = nullptr, evGh = nullptr;
    static bool attr_done = false;
    if (!s1) {
        cudaStreamCreateWithFlags(&s1, cudaStreamNonBlocking);
        cudaEventCreateWithFlags(&evX,  cudaEventDisableTiming);
        cudaEventCreateWithFlags(&evWhT, cudaEventDisableTiming);
        cudaEventCreateWithFlags(&evGh, cudaEventDisableTiming);
    }
    if (!attr_done) {
        cudaFuncSetAttribute(attn_mma, cudaFuncAttributeMaxDynamicSharedMemorySize,
                             ATTN_SMEM_WORDS * 4);
        cudaFuncSetAttribute(whT_f16, cudaFuncAttributeMaxDynamicSharedMemorySize,
                             WT_SMEM_BYTES);
        cudaFuncSetAttribute(gh_gemm_f16, cudaFuncAttributeMaxDynamicSharedMemorySize,
                             GH_SMEM_BYTES);
        cudaFuncSetAttribute(gru_gemm, cudaFuncAttributeMaxDynamicSharedMemorySize,
                             GRU_SMEM_BYTES);
        attr_done = true;
    }

    // ---- stream 0 (default): conversions, then stats chain
    cvt_all<<<2240, 256>>>(x, px16, w_ih, pwih16, w_hh, pwhh16);
    cudaEventRecord(evX, 0);                 // x16 / wih16 / whh16 ready

    // ---- fork stream 1: WhT + gh chains (independent of stats chain)
    cudaStreamWaitEvent(s1, evX, 0);
    cvt_wT<<<dim3(HH / 32, DD / 32), dim3(32, 8), 0, s1>>>(W, pwt16);
    whT_f16<<<dim3(ROWS / 128, HH / 128), 256, WT_SMEM_BYTES, s1>>>(pwt16, px16, pWhT);
    cudaEventRecord(evWhT, s1);
    gh_gemm_f16<<<dim3(3 * HH / 192, ROWS / 128), 256, GH_SMEM_BYTES, s1>>>(
        px16, pwhh16, b_hh, pgh16, 3 * HH, HH);
    cudaEventRecord(evGh, s1);

    // ---- stream 0: stats chain (overlaps with stream 1)
    av_gemv<<<32, 256>>>(W, a, pav);
    wh12_x<<<ROWS / 8, 256>>>(px16, pav, pWh1, pWh2);
    pack_stats<<<ROWS, 256>>>(adj, pWh1, pWh2, pws, prs);

    // ---- join: attention needs WhT; gru needs gh
    cudaStreamWaitEvent(0, evWhT, 0);
    attn_mma<<<dim3(NN_ / 128, HH / 128, BB), 256, ATTN_SMEM_WORDS * 4>>>(
        pWhT, pws, prs, pgo16);

    cudaStreamWaitEvent(0, evGh, 0);
    gru_gemm<<<dim3(HH / 32, ROWS / 128), 256, GRU_SMEM_BYTES>>>(
        pgo16, pwih16, b_ih, pgh16, x, out);
}

// round 17
// speedup vs baseline: 1.0708x; 1.0087x over previous
#include <cuda_runtime.h>
#include <cuda_fp16.h>
#include <cstdint>
#include <math.h>

// Problem constants
#define BB 8
#define NN_ 2048
#define DD 256
#define HH 256
#define ROWS (BB*NN_)          // 16384
#define ALPHA 0.2f

// ---------------- scratch (device globals) ---------------------------------
__device__ __half   g_WhT [(size_t)ROWS*HH];     // fp16 Wh^T [b][h][i]
__device__ __half   g_ws  [(size_t)ROWS*NN_];    // fp16 attention weights [r][j]
__device__ __half   g_go16[(size_t)ROWS*HH];     // fp16 graph_out
__device__ __half   g_gh16[(size_t)ROWS*3*HH];   // fp16 gh
__device__ __half   g_x16 [(size_t)ROWS*HH];     // fp16 x
__device__ __half   g_wih16[3*HH*HH];
__device__ __half   g_whh16[3*HH*HH];
__device__ __half   g_wt16[HH*DD];               // fp16 W^T [h][d]
__device__ float    g_av [2*DD];                 // W@a1 | W@a2
__device__ float    g_Wh1[ROWS];
__device__ float    g_Wh2[ROWS];
__device__ float    g_rs [ROWS];

// ---------------- helpers ---------------------------------------------------
__device__ __forceinline__ void mma_f16(float* d, const uint32_t* a, const uint32_t* b) {
    asm volatile("mma.sync.aligned.m16n8k16.row.col.f32.f16.f16.f32 "
        "{%0,%1,%2,%3}, {%4,%5,%6,%7}, {%8,%9}, {%0,%1,%2,%3};\n"
        : "+f"(d[0]), "+f"(d[1]), "+f"(d[2]), "+f"(d[3])
        : "r"(a[0]), "r"(a[1]), "r"(a[2]), "r"(a[3]), "r"(b[0]), "r"(b[1]));
}
__device__ __forceinline__ void cp16(void* smem, const void* gmem) {
    uint32_t s = (uint32_t)__cvta_generic_to_shared(smem);
    asm volatile("cp.async.cg.shared.global [%0], [%1], 16;\n" :: "r"(s), "l"(gmem));
}
__device__ __forceinline__ void cp_commit() { asm volatile("cp.async.commit_group;\n" ::: "memory"); }
__device__ __forceinline__ void cp_wait0()  { asm volatile("cp.async.wait_group 0;\n" ::: "memory"); }
__device__ __forceinline__ void cp_wait1()  { asm volatile("cp.async.wait_group 1;\n" ::: "memory"); }

#define AST 36     // [row][k-word] stride: frag LDS bank = (4g+t)%32, conflict-free

// ---------------- fused fp32 -> fp16 converter (x, w_ih, w_hh in one) ------
__global__ __launch_bounds__(256)
void cvt_all(const float* __restrict__ x,  __half* __restrict__ x16,
             const float* __restrict__ wi, __half* __restrict__ wi16,
             const float* __restrict__ wh, __half* __restrict__ wh16)
{
    int bid = blockIdx.x;
    const float* src; __half* dst; int base;
    if (bid < 2048)      { src = x;  dst = x16;  base = bid * 2048; }
    else if (bid < 2144) { src = wi; dst = wi16; base = (bid - 2048) * 2048; }
    else                 { src = wh; dst = wh16; base = (bid - 2144) * 2048; }
    int i = base + threadIdx.x * 8;
    float4 v0 = *(const float4*)(src + i);
    float4 v1 = *(const float4*)(src + i + 4);
    __half2 h[4] = { __floats2half2_rn(v0.x, v0.y), __floats2half2_rn(v0.z, v0.w),
                     __floats2half2_rn(v1.x, v1.y), __floats2half2_rn(v1.z, v1.w) };
    *(uint4*)(dst + i) = *(uint4*)h;
}

// ---------------- W[d][h] -> WT16[h][d] fp16 transpose ---------------------
__global__ void cvt_wT(const float* __restrict__ W, __half* __restrict__ WT)
{
    __shared__ float tle[32][33];
    const int h0 = blockIdx.x * 32, d0 = blockIdx.y * 32;
    const int tx = threadIdx.x, ty = threadIdx.y;    // 32 x 8
#pragma unroll
    for (int k = 0; k < 4; k++)
        tle[ty + 8 * k][tx] = W[(size_t)(d0 + ty + 8 * k) * HH + h0 + tx];
    __syncthreads();
#pragma unroll
    for (int k = 0; k < 4; k++)
        WT[(size_t)(h0 + ty + 8 * k) * DD + d0 + tx] = __float2half(tle[tx][ty + 8 * k]);
}

// ---------------- av = [W@a1 | W@a2]  (tiny fp32 GEMV) ---------------------
__global__ __launch_bounds__(256)
void av_gemv(const float* __restrict__ W, const float* __restrict__ a,
             float* __restrict__ av)
{
    const int warp = threadIdx.x >> 5, lane = threadIdx.x & 31;
    const int d = blockIdx.x * 8 + warp;           // 0..255
    const float* wr = W + (size_t)d * HH + lane * 8;
    float4 w0 = *(const float4*)wr;
    float4 w1 = *(const float4*)(wr + 4);
    const float* a1 = a + lane * 8;
    const float* a2 = a + HH + lane * 8;
    float4 p0 = *(const float4*)a1, p1 = *(const float4*)(a1 + 4);
    float4 q0 = *(const float4*)a2, q1 = *(const float4*)(a2 + 4);
    float s1 = w0.x*p0.x + w0.y*p0.y + w0.z*p0.z + w0.w*p0.w
             + w1.x*p1.x + w1.y*p1.y + w1.z*p1.z + w1.w*p1.w;
    float s2 = w0.x*q0.x + w0.y*q0.y + w0.z*q0.z + w0.w*q0.w
             + w1.x*q1.x + w1.y*q1.y + w1.z*q1.z + w1.w*q1.w;
#pragma unroll
    for (int o = 16; o; o >>= 1) {
        s1 += __shfl_xor_sync(0xffffffffu, s1, o);
        s2 += __shfl_xor_sync(0xffffffffu, s2, o);
    }
    if (lane == 0) { av[d] = s1; av[DD + d] = s2; }
}

// ---------------- Wh1/Wh2 via associativity: Wh1 = x16 . av1 ---------------
__global__ __launch_bounds__(256)
void wh12_x(const __half* __restrict__ x16, const float* __restrict__ av,
            float* __restrict__ Wh1, float* __restrict__ Wh2)
{
    const int warp = threadIdx.x >> 5, lane = threadIdx.x & 31;
    const int r = blockIdx.x * 8 + warp;
    const __half* xr = x16 + (size_t)r * DD + lane * 8;
    uint4 xv = *(const uint4*)xr;                  // 8 halves
    const __half2* xh = (const __half2*)&xv;
    const float* a1 = av + lane * 8;
    const float* a2 = av + DD + lane * 8;
    float4 p0 = *(const float4*)a1, p1 = *(const float4*)(a1 + 4);
    float4 q0 = *(const float4*)a2, q1 = *(const float4*)(a2 + 4);
    float2 x0 = __half22float2(xh[0]);
    float2 x1 = __half22float2(xh[1]);
    float2 x2 = __half22float2(xh[2]);
    float2 x3 = __half22float2(xh[3]);
    float s1 = x0.x*p0.x + x0.y*p0.y + x1.x*p0.z + x1.y*p0.w
             + x2.x*p1.x + x2.y*p1.y + x3.x*p1.z + x3.y*p1.w;
    float s2 = x0.x*q0.x + x0.y*q0.y + x1.x*q0.z + x1.y*q0.w
             + x2.x*q1.x + x2.y*q1.y + x3.x*q1.z + x3.y*q1.w;
#pragma unroll
    for (int o = 16; o; o >>= 1) {
        s1 += __shfl_xor_sync(0xffffffffu, s1, o);
        s2 += __shfl_xor_sync(0xffffffffu, s2, o);
    }
    if (lane == 0) { Wh1[r] = s1; Wh2[r] = s2; }
}

// ---------------- whT GEMM: WhT[b][h][i] = WT16 @ x16^T (fp16 MMA) ---------
#define WT_SMEM_BYTES (4 * 128 * AST * 4)
__global__ __launch_bounds__(256, 2)
void whT_f16(const __half* __restrict__ WT16, const __half* __restrict__ x16,
             __half* __restrict__ WhT)
{
    extern __shared__ uint32_t dsm[];
    uint32_t* As[2] = { dsm, dsm + 128 * AST };
    uint32_t* Bs[2] = { dsm + 2 * 128 * AST, dsm + 3 * 128 * AST };

    const int tid  = threadIdx.x;
    const int warp = tid >> 5, lane = tid & 31;
    const int g = lane >> 2, t = lane & 3;
    const int wm = warp & 1, wn = warp >> 1;   // 2 m x 4 n
    const int m0 = blockIdx.y * 128;           // h block
    const int n0 = blockIdx.x * 128;           // global row block
    const int b  = n0 >> 11;
    const int ib = n0 & (NN_ - 1);

    auto issue = [&](int T, int st) {
#pragma unroll
        for (int s = 0; s < 4; s++) {
            int f = tid + 256 * s;
            int m = f >> 3, grp = f & 7;
            cp16(&As[st][m * AST + grp * 4], WT16 + (size_t)(m0 + m) * DD + T * 64 + grp * 8);
        }
#pragma unroll
        for (int s = 0; s < 4; s++) {
            int f = tid + 256 * s;
            int n = f >> 3, grp = f & 7;
            cp16(&Bs[st][n * AST + grp * 4], x16 + (size_t)(n0 + n) * DD + T * 64 + grp * 8);
        }
    };

    float acc[4][4][4] = {};

    issue(0, 0); cp_commit();

    for (int T = 0; T < 4; T++) {
        const int st = T & 1;
        if (T + 1 < 4) { issue(T + 1, st ^ 1); cp_commit(); cp_wait1(); }
        else           { cp_wait0(); }
        __syncthreads();

#pragma unroll
        for (int ks = 0; ks < 4; ks++) {
            const int kk = ks * 8;
            uint32_t af[4][4], bf[4][2];
#pragma unroll
            for (int mf = 0; mf < 4; mf++) {
                int r0 = wm * 64 + mf * 16 + g;
                af[mf][0] = As[st][(r0    ) * AST + kk + t];
                af[mf][1] = As[st][(r0 + 8) * AST + kk + t];
                af[mf][2] = As[st][(r0    ) * AST + kk + t + 4];
                af[mf][3] = As[st][(r0 + 8) * AST + kk + t + 4];
            }
#pragma unroll
            for (int nf = 0; nf < 4; nf++) {
                int c0 = wn * 32 + nf * 8 + g;
                bf[nf][0] = Bs[st][c0 * AST + kk + t];
                bf[nf][1] = Bs[st][c0 * AST + kk + t + 4];
            }
#pragma unroll
            for (int mf = 0; mf < 4; mf++)
#pragma unroll
                for (int nf = 0; nf < 4; nf++)
                    mma_f16(acc[mf][nf], af[mf], bf[nf]);
        }
        __syncthreads();
    }

#pragma unroll
    for (int mf = 0; mf < 4; mf++) {
        int h = m0 + wm * 64 + mf * 16 + g;
#pragma unroll
        for (int nf = 0; nf < 4; nf++) {
            int i = ib + wn * 32 + nf * 8 + 2 * t;
            *(__half2*)(WhT + (size_t)(b * HH + h)     * NN_ + i) =
                __floats2half2_rn(acc[mf][nf][0], acc[mf][nf][1]);
            *(__half2*)(WhT + (size_t)(b * HH + h + 8) * NN_ + i) =
                __floats2half2_rn(acc[mf][nf][2], acc[mf][nf][3]);
        }
    }
}

// ---------------- fused: adj -> masked softmax stats + fp16 ws matrix ------
__global__ __launch_bounds__(256)
void pack_stats(const int* __restrict__ adj, const float* __restrict__ Wh1,
                const float* __restrict__ Wh2, __half* __restrict__ ws,
                float* __restrict__ rsum)
{
    const int r = blockIdx.x;
    const int b = r >> 11;
    const int tid = threadIdx.x;
    const float w1 = Wh1[r];
    const float* Wh2b = Wh2 + (b << 11);

    const int4* ap = (const int4*)(adj + (size_t)r * NN_ + tid * 8);
    int4 a0 = ap[0], a1 = ap[1];
    float4 w0 = *(const float4*)(Wh2b + tid * 8);
    float4 w1v = *(const float4*)(Wh2b + tid * 8 + 4);

    int m[8] = { a0.x > 0, a0.y > 0, a0.z > 0, a0.w > 0,
                 a1.x > 0, a1.y > 0, a1.z > 0, a1.w > 0 };
    float wv[8] = { w0.x, w0.y, w0.z, w0.w, w1v.x, w1v.y, w1v.z, w1v.w };

    float lrv[8];
    float mx = -INFINITY;
#pragma unroll
    for (int k = 0; k < 8; k++) {
        float sv = w1 + wv[k];
        float lr = sv > 0.f ? sv : ALPHA * sv;
        lrv[k] = m[k] ? lr : -INFINITY;
        mx = fmaxf(mx, lrv[k]);
    }

    __shared__ float sred[8];
#pragma unroll
    for (int o = 16; o; o >>= 1) mx = fmaxf(mx, __shfl_xor_sync(0xffffffffu, mx, o));
    if ((tid & 31) == 0) sred[tid >> 5] = mx;
    __syncthreads();
    if (tid == 0) {
        float v = sred[0];
#pragma unroll
        for (int w = 1; w < 8; w++) v = fmaxf(v, sred[w]);
        sred[0] = v;
    }
    __syncthreads();
    mx = sred[0];

    float ev[8];
    float sum = 0.f;
#pragma unroll
    for (int k = 0; k < 8; k++) { ev[k] = __expf(lrv[k] - mx); sum += ev[k]; }
    __half2 hq[4];
#pragma unroll
    for (int k = 0; k < 4; k++) hq[k] = __floats2half2_rn(ev[2*k], ev[2*k+1]);
    *(uint4*)(ws + (size_t)r * NN_ + tid * 8) = *(uint4*)hq;

#pragma unroll
    for (int o = 16; o; o >>= 1) sum += __shfl_xor_sync(0xffffffffu, sum, o);
    __syncthreads();
    if ((tid & 31) == 0) sred[tid >> 5] = sum;
    __syncthreads();
    if (tid == 0) {
        float v = 0.f;
#pragma unroll
        for (int w = 0; w < 8; w++) v += sred[w];
        rsum[r] = v;
    }
}

// ---------------- attention GEMM: fp16 MMA, 128i x 128h, 2-stage (R13) -----
#define ATTN_SMEM_WORDS (4*128*AST + 128)
__global__ __launch_bounds__(256, 2)
void attn_mma(const __half* __restrict__ WhT, const __half* __restrict__ ws,
              const float* __restrict__ rsum, __half* __restrict__ go)
{
    extern __shared__ uint32_t dsm[];
    uint32_t* wsA[2] = { dsm, dsm + 128 * AST };                      // [i][j-half2]
    uint32_t* WhB[2] = { dsm + 2*128*AST, dsm + 3*128*AST };          // [h][j-half2]
    float* fis = (float*)(dsm + 4*128*AST);

    const int b = blockIdx.z, i0 = blockIdx.x * 128, h0 = blockIdx.y * 128;
    const int tid = threadIdx.x;
    const int warp = tid >> 5, lane = tid & 31;
    const int g = lane >> 2, t = lane & 3;
    const int wm = warp >> 2, wn = warp & 3;   // 2 i-warps x 4 h-warps

    const __half* WhT_b = WhT + (size_t)(b * HH + h0) * NN_;
    const __half* ws_b  = ws  + (size_t)(b * NN_ + i0) * NN_;

    if (tid < 128) fis[tid] = 1.0f / rsum[b * NN_ + i0 + tid];
    __syncthreads();

    auto issue = [&](int T, int st) {
        const __half* asrc = ws_b + T * 64;
#pragma unroll
        for (int s = 0; s < 4; s++) {            // 1024 cp16: 128i x 64j
            int idx = tid + 256 * s;
            int i = idx >> 3, grp = idx & 7;
            cp16(&wsA[st][i * AST + grp * 4], asrc + (size_t)i * NN_ + grp * 8);
        }
        const __half* wsrc = WhT_b + T * 64;
#pragma unroll
        for (int s = 0; s < 4; s++) {            // 1024 cp16: 128h x 64j
            int idx = tid + 256 * s;
            int h = idx >> 3, grp = idx & 7;
            cp16(&WhB[st][h * AST + grp * 4], wsrc + (size_t)h * NN_ + grp * 8);
        }
    };

    float acc[4][4][4] = {};

    issue(0, 0); cp_commit(); cp_wait0(); __syncthreads();

    for (int T = 0; T < NN_ / 64; T++) {
        const int st = T & 1, nst = st ^ 1;
        if (T + 1 < NN_ / 64) issue(T + 1, nst);
        cp_commit();

#pragma unroll
        for (int ks = 0; ks < 4; ks++) {
            const int kk = ks * 8;
            uint32_t af[4][4], bf[4][2];
#pragma unroll
            for (int mf = 0; mf < 4; mf++) {
                int r0 = wm * 64 + mf * 16 + g;
                af[mf][0] = wsA[st][(r0    ) * AST + kk + t];
                af[mf][1] = wsA[st][(r0 + 8) * AST + kk + t];
                af[mf][2] = wsA[st][(r0    ) * AST + kk + t + 4];
                af[mf][3] = wsA[st][(r0 + 8) * AST + kk + t + 4];
            }
#pragma unroll
            for (int nf = 0; nf < 4; nf++) {
                int c0 = wn * 32 + nf * 8 + g;
                bf[nf][0] = WhB[st][c0 * AST + kk + t];
                bf[nf][1] = WhB[st][c0 * AST + kk + t + 4];
            }
#pragma unroll
            for (int mf = 0; mf < 4; mf++)
#pragma unroll
                for (int nf = 0; nf < 4; nf++)
                    mma_f16(acc[mf][nf], af[mf], bf[nf]);
        }
        cp_wait0(); __syncthreads();
    }

#pragma unroll
    for (int mf = 0; mf < 4; mf++) {
        int il = wm * 64 + mf * 16 + g;
        float s0 = fis[il], s1 = fis[il + 8];
        __half* o0 = go + (size_t)(b * NN_ + i0 + il)     * HH + h0;
        __half* o1 = go + (size_t)(b * NN_ + i0 + il + 8) * HH + h0;
#pragma unroll
        for (int nf = 0; nf < 4; nf++) {
            int hc = wn * 32 + nf * 8 + 2 * t;
            *(__half2*)(o0 + hc) = __floats2half2_rn(acc[mf][nf][0] * s0, acc[mf][nf][1] * s0);
            *(__half2*)(o1 + hc) = __floats2half2_rn(acc[mf][nf][2] * s1, acc[mf][nf][3] * s1);
        }
    }
}

// ---------------- gh GEMM: fp16 MMA, 128m x 192n tiles, 2-stage ------------
#define GH_SMEM_BYTES (2 * (128 + 192) * AST * 4)
__global__ __launch_bounds__(256, 2)
void gh_gemm_f16(const __half* __restrict__ A16, const __half* __restrict__ B16,
                 const float* __restrict__ bias, __half* __restrict__ C16,
                 int N, int K)
{
    extern __shared__ uint32_t dsm[];
    uint32_t* As[2] = { dsm, dsm + 128 * AST };
    uint32_t* Bs[2] = { dsm + 2 * 128 * AST, dsm + 2 * 128 * AST + 192 * AST };

    const int tid  = threadIdx.x;
    const int warp = tid >> 5, lane = tid & 31;
    const int g = lane >> 2, t = lane & 3;
    const int wm = warp & 1, wn = warp >> 1;   // 2 m x 4 n (48 cols each)
    const int m0 = blockIdx.y * 128, n0 = blockIdx.x * 192;
    const int KT = K / 64;

    auto issue = [&](int T, int st) {
#pragma unroll
        for (int s = 0; s < 4; s++) {
            int f = tid + 256 * s;
            int m = f >> 3, grp = f & 7;
            cp16(&As[st][m * AST + grp * 4], A16 + (size_t)(m0 + m) * K + T * 64 + grp * 8);
        }
#pragma unroll
        for (int s = 0; s < 6; s++) {
            int f = tid + 256 * s;             // 1536 cp16: 192n x 64k
            int n = f >> 3, grp = f & 7;
            cp16(&Bs[st][n * AST + grp * 4], B16 + (size_t)(n0 + n) * K + T * 64 + grp * 8);
        }
    };

    float acc[4][6][4] = {};

    issue(0, 0); cp_commit();

    for (int T = 0; T < KT; T++) {
        const int st = T & 1;
        if (T + 1 < KT) { issue(T + 1, st ^ 1); cp_commit(); cp_wait1(); }
        else            { cp_wait0(); }
        __syncthreads();

#pragma unroll
        for (int ks = 0; ks < 4; ks++) {
            const int kk = ks * 8;
            uint32_t af[4][4], bf[6][2];
#pragma unroll
            for (int mf = 0; mf < 4; mf++) {
                int r0 = wm * 64 + mf * 16 + g;
                af[mf][0] = As[st][(r0    ) * AST + kk + t];
                af[mf][1] = As[st][(r0 + 8) * AST + kk + t];
                af[mf][2] = As[st][(r0    ) * AST + kk + t + 4];
                af[mf][3] = As[st][(r0 + 8) * AST + kk + t + 4];
            }
#pragma unroll
            for (int nf = 0; nf < 6; nf++) {
                int c0 = wn * 48 + nf * 8 + g;
                bf[nf][0] = Bs[st][c0 * AST + kk + t];
                bf[nf][1] = Bs[st][c0 * AST + kk + t + 4];
            }
#pragma unroll
            for (int mf = 0; mf < 4; mf++)
#pragma unroll
                for (int nf = 0; nf < 6; nf++)
                    mma_f16(acc[mf][nf], af[mf], bf[nf]);
        }
        __syncthreads();
    }

#pragma unroll
    for (int mf = 0; mf < 4; mf++) {
        int row = m0 + wm * 64 + mf * 16 + g;
#pragma unroll
        for (int nf = 0; nf < 6; nf++) {
            int col = n0 + wn * 48 + nf * 8 + 2 * t;
            float b0v = bias[col], b1v = bias[col + 1];
            *(__half2*)(C16 + (size_t)row * N + col) =
                __floats2half2_rn(acc[mf][nf][0] + b0v, acc[mf][nf][1] + b1v);
            *(__half2*)(C16 + (size_t)(row + 8) * N + col) =
                __floats2half2_rn(acc[mf][nf][2] + b0v, acc[mf][nf][3] + b1v);
        }
    }
}

// ---------------- fused gi GEMM (fp16, 3 gates) + GRU, 2-stage -------------
#define GRU_SMEM_BYTES ((2*128*AST + 2*3*32*AST) * 4)
__global__ __launch_bounds__(256, 2)
void gru_gemm(const __half* __restrict__ go, const __half* __restrict__ wih,
              const float* __restrict__ b_ih, const __half* __restrict__ gh,
              const float* __restrict__ x, float* __restrict__ out)
{
    extern __shared__ uint32_t dsm[];
    uint32_t* As[2] = { dsm, dsm + 128 * AST };
    uint32_t* Bbase  = dsm + 2 * 128 * AST;   // [st][gate][32*AST]

    const int tid  = threadIdx.x;
    const int warp = tid >> 5, lane = tid & 31;
    const int g = lane >> 2, t = lane & 3;
    const int wm = warp >> 1, wn = warp & 1;  // 4 m-warps x 2 n-warps
    const int m0 = blockIdx.y * 128;
    const int h0 = blockIdx.x * 32;

    auto issue = [&](int T, int st) {
#pragma unroll
        for (int s = 0; s < 4; s++) {
            int f = tid + 256 * s;
            int m = f >> 3, grp = f & 7;
            cp16(&As[st][m * AST + grp * 4], go + (size_t)(m0 + m) * HH + T * 64 + grp * 8);
        }
        uint32_t* Bst = Bbase + st * 3 * 32 * AST;
#pragma unroll
        for (int s = 0; s < 3; s++) {
            int idx = tid + 256 * s;            // 0..767
            int gate = idx >> 8;
            int r = idx & 255;
            int n = r >> 3, grp = r & 7;
            cp16(&Bst[gate * 32 * AST + n * AST + grp * 4],
                 wih + (size_t)(gate * HH + h0 + n) * HH + T * 64 + grp * 8);
        }
    };

    float acc[3][2][2][4] = {};

    issue(0, 0); cp_commit();

    for (int T = 0; T < 4; T++) {
        const int st = T & 1;
        if (T + 1 < 4) { issue(T + 1, st ^ 1); cp_commit(); cp_wait1(); }
        else           { cp_wait0(); }
        __syncthreads();
        uint32_t* Bst = Bbase + st * 3 * 32 * AST;

#pragma unroll
        for (int ks = 0; ks < 4; ks++) {
            const int kk = ks * 8;
            uint32_t af[2][4], bf[3][2][2];
#pragma unroll
            for (int mf = 0; mf < 2; mf++) {
                int r0 = wm * 32 + mf * 16 + g;
                af[mf][0] = As[st][(r0    ) * AST + kk + t];
                af[mf][1] = As[st][(r0 + 8) * AST + kk + t];
                af[mf][2] = As[st][(r0    ) * AST + kk + t + 4];
                af[mf][3] = As[st][(r0 + 8) * AST + kk + t + 4];
            }
#pragma unroll
            for (int gate = 0; gate < 3; gate++)
#pragma unroll
                for (int nf = 0; nf < 2; nf++) {
                    int c0 = wn * 16 + nf * 8 + g;
                    bf[gate][nf][0] = Bst[gate * 32 * AST + c0 * AST + kk + t];
                    bf[gate][nf][1] = Bst[gate * 32 * AST + c0 * AST + kk + t + 4];
                }
#pragma unroll
            for (int gate = 0; gate < 3; gate++)
#pragma unroll
                for (int mf = 0; mf < 2; mf++)
#pragma unroll
                    for (int nf = 0; nf < 2; nf++)
                        mma_f16(acc[gate][mf][nf], af[mf], bf[gate][nf]);
        }
        __syncthreads();
    }

    // ---- GRU epilogue
#pragma unroll
    for (int mf = 0; mf < 2; mf++) {
#pragma unroll
        for (int nf = 0; nf < 2; nf++) {
            int col = h0 + wn * 16 + nf * 8 + 2 * t;
            float br0 = b_ih[col],            br1 = b_ih[col + 1];
            float bz0 = b_ih[HH + col],       bz1 = b_ih[HH + col + 1];
            float bn0 = b_ih[2 * HH + col],   bn1 = b_ih[2 * HH + col + 1];
#pragma unroll
            for (int pr = 0; pr < 2; pr++) {
                int row = m0 + wm * 32 + mf * 16 + g + pr * 8;
                const __half* ghr = gh + (size_t)row * (3 * HH);
                float2 hr = __half22float2(*(const __half2*)(ghr + col));
                float2 hz = __half22float2(*(const __half2*)(ghr + HH + col));
                float2 hn = __half22float2(*(const __half2*)(ghr + 2 * HH + col));
                float2 xv = *(const float2*)(x + (size_t)row * HH + col);

                float ir0 = acc[0][mf][nf][pr*2+0] + br0, ir1 = acc[0][mf][nf][pr*2+1] + br1;
                float iz0 = acc[1][mf][nf][pr*2+0] + bz0, iz1 = acc[1][mf][nf][pr*2+1] + bz1;
                float in0 = acc[2][mf][nf][pr*2+0] + bn0, in1 = acc[2][mf][nf][pr*2+1] + bn1;

                float r0g = 1.f / (1.f + __expf(-(ir0 + hr.x)));
                float r1g = 1.f / (1.f + __expf(-(ir1 + hr.y)));
                float z0g = 1.f / (1.f + __expf(-(iz0 + hz.x)));
                float z1g = 1.f / (1.f + __expf(-(iz1 + hz.y)));
                float n0g = tanhf(in0 + r0g * hn.x);
                float n1g = tanhf(in1 + r1g * hn.y);
                float2 o;
                o.x = (1.f - z0g) * n0g + z0g * xv.x;
                o.y = (1.f - z1g) * n1g + z1g * xv.y;
                *(float2*)(out + (size_t)row * HH + col) = o;
            }
        }
    }
}

// ---------------- launch: dual-stream fork/join ----------------------------
extern "C" void kernel_launch(void* const* d_in, const int* in_sizes, int n_in,
                              void* d_out, int out_size)
{
    const int*   adj  = (const int*)  d_in[0];
    const float* x    = (const float*)d_in[1];
    const float* W    = (const float*)d_in[2];
    const float* a    = (const float*)d_in[3];
    const float* w_ih = (const float*)d_in[4];
    const float* w_hh = (const float*)d_in[5];
    const float* b_ih = (const float*)d_in[6];
    const float* b_hh = (const float*)d_in[7];
    float* out = (float*)d_out;

    float *pWh1, *pWh2, *prs, *pav;
    __half *pWhT, *pws, *pgo16, *pgh16, *px16, *pwih16, *pwhh16, *pwt16;
    cudaGetSymbolAddress((void**)&pWhT,  g_WhT);
    cudaGetSymbolAddress((void**)&pws,   g_ws);
    cudaGetSymbolAddress((void**)&pgo16, g_go16);
    cudaGetSymbolAddress((void**)&pgh16, g_gh16);
    cudaGetSymbolAddress((void**)&px16,  g_x16);
    cudaGetSymbolAddress((void**)&pwih16, g_wih16);
    cudaGetSymbolAddress((void**)&pwhh16, g_whh16);
    cudaGetSymbolAddress((void**)&pwt16,  g_wt16);
    cudaGetSymbolAddress((void**)&pav,  g_av);
    cudaGetSymbolAddress((void**)&pWh1, g_Wh1);
    cudaGetSymbolAddress((void**)&pWh2, g_Wh2);
    cudaGetSymbolAddress((void**)&prs,  g_rs);

    // One-time resources (created on the first, non-captured correctness call)
    static cudaStream_t s1 = nullptr;
    static cudaEvent_t evX = nullptr, evWhT = nullptr, evGh = nullptr;
    static bool attr_done = false;
    if (!s1) {
        cudaStreamCreateWithFlags(&s1, cudaStreamNonBlocking);
        cudaEventCreateWithFlags(&evX,  cudaEventDisableTiming);
        cudaEventCreateWithFlags(&evWhT, cudaEventDisableTiming);
        cudaEventCreateWithFlags(&evGh, cudaEventDisableTiming);
    }
    if (!attr_done) {
        cudaFuncSetAttribute(attn_mma, cudaFuncAttributeMaxDynamicSharedMemorySize,
                             ATTN_SMEM_WORDS * 4);
        cudaFuncSetAttribute(whT_f16, cudaFuncAttributeMaxDynamicSharedMemorySize,
                             WT_SMEM_BYTES);
        cudaFuncSetAttribute(gh_gemm_f16, cudaFuncAttributeMaxDynamicSharedMemorySize,
                             GH_SMEM_BYTES);
        cudaFuncSetAttribute(gru_gemm, cudaFuncAttributeMaxDynamicSharedMemorySize,
                             GRU_SMEM_BYTES);
        attr_done = true;
    }

    // ---- stream 0 (default): conversions, then stats chain
    cvt_all<<<2240, 256>>>(x, px16, w_ih, pwih16, w_hh, pwhh16);
    cudaEventRecord(evX, 0);                 // x16 / wih16 / whh16 ready

    // ---- fork stream 1: WhT + gh chains (independent of stats chain)
    cudaStreamWaitEvent(s1, evX, 0);
    cvt_wT<<<dim3(HH / 32, DD / 32), dim3(32, 8), 0, s1>>>(W, pwt16);
    whT_f16<<<dim3(ROWS / 128, HH / 128), 256, WT_SMEM_BYTES, s1>>>(pwt16, px16, pWhT);
    cudaEventRecord(evWhT, s1);
    gh_gemm_f16<<<dim3(3 * HH / 192, ROWS / 128), 256, GH_SMEM_BYTES, s1>>>(
        px16, pwhh16, b_hh, pgh16, 3 * HH, HH);
    cudaEventRecord(evGh, s1);

    // ---- stream 0: stats chain (overlaps with stream 1)
    av_gemv<<<32, 256>>>(W, a, pav);
    wh12_x<<<ROWS / 8, 256>>>(px16, pav, pWh1, pWh2);
    pack_stats<<<ROWS, 256>>>(adj, pWh1, pWh2, pws, prs);

    // ---- join: attention needs WhT; gru needs gh
    cudaStreamWaitEvent(0, evWhT, 0);
    attn_mma<<<dim3(NN_ / 128, HH / 128, BB), 256, ATTN_SMEM_WORDS * 4>>>(
        pWhT, pws, prs, pgo16);

    cudaStreamWaitEvent(0, evGh, 0);
    gru_gemm<<<dim3(HH / 32, ROWS / 128), 256, GRU_SMEM_BYTES>>>(
        pgo16, pwih16, b_ih, pgh16, x, out);
}